// round 15
// baseline (speedup 1.0000x reference)
#include <cuda_runtime.h>
#include <cuda_bf16.h>
#include <cstdint>
#include <cstddef>

// ============================================================================
// TripletSTDP: B=32, T=512, N_PRE=N_POST=1024.
// wu = (1/(B*T)) * (A @ B^T), K = 2*B*T = 32768
//   A[m][k]: k<16384 -> R trace of pre (decayed), k>=16384 -> pre spike
//   B[n][k]: k<16384 -> post spike,               k>=16384 -> -O trace of post
// A/B PRE-PERMUTED in mma.m16n8k16 fragment order (bf16).
// Overlap: scan(b0-15) -> [gemm slices {0,1,4,5} || scan(b16-31)] -> gemm
// slices {2,3,6,7} -> reduce. Split-K=8.
// GEMM: WARP-SPECIALIZED. 8 consumer warps (2Mx4N, warp tile 64x64) + 2
// producer warps; 4-stage mbarrier ring; cp.async.mbarrier.arrive.NOINC
// (default form nets zero against init count -> R14 deadlock; fixed).
// ============================================================================

static __device__ __align__(128) __nv_bfloat16 g_A[1024ull * 32768ull]; // 64 MB
static __device__ __align__(128) __nv_bfloat16 g_B[1024ull * 32768ull]; // 64 MB
static __device__ __align__(128) float         g_WS[8ull * 1024ull * 1024ull]; // 8 split-K partials

// ---------------------------------------------------------------------------
__device__ __forceinline__ void mma_bf16(float* d, const uint32_t* a,
                                         uint32_t b0, uint32_t b1) {
    asm volatile(
        "mma.sync.aligned.m16n8k16.row.col.f32.bf16.bf16.f32 "
        "{%0,%1,%2,%3}, {%4,%5,%6,%7}, {%8,%9}, {%0,%1,%2,%3};"
        : "+f"(d[0]), "+f"(d[1]), "+f"(d[2]), "+f"(d[3])
        : "r"(a[0]), "r"(a[1]), "r"(a[2]), "r"(a[3]), "r"(b0), "r"(b1));
}
__device__ __forceinline__ uint32_t smem_u32(const void* p) {
    uint32_t a;
    asm("{ .reg .u64 t; cvta.to.shared.u64 t, %1; cvt.u32.u64 %0, t; }" : "=r"(a) : "l"(p));
    return a;
}
__device__ __forceinline__ void cp16(uint32_t dst, const void* src) {
    asm volatile("cp.async.cg.shared.global [%0], [%1], 16;" :: "r"(dst), "l"(src));
}
__device__ __forceinline__ void mbar_init(uint32_t a, uint32_t cnt) {
    asm volatile("mbarrier.init.shared.b64 [%0], %1;" :: "r"(a), "r"(cnt) : "memory");
}
__device__ __forceinline__ void mbar_wait(uint32_t a, uint32_t ph) {
    asm volatile(
        "{\n\t.reg .pred P;\n\t"
        "LAB_%=:\n\t"
        "mbarrier.try_wait.parity.acquire.cta.shared::cta.b64 P, [%0], %1;\n\t"
        "@!P bra LAB_%=;\n\t}"
        :: "r"(a), "r"(ph) : "memory");
}
__device__ __forceinline__ void mbar_arrive(uint32_t a) {
    asm volatile("mbarrier.arrive.shared.b64 _, [%0];" :: "r"(a) : "memory");
}
__device__ __forceinline__ void cp_async_mbar_arrive_noinc(uint32_t a) {
    asm volatile("cp.async.mbarrier.arrive.noinc.shared.b64 [%0];" :: "r"(a) : "memory");
}

// ---------------------------------------------------------------------------
// Kernel 1: trace scan + fragment-layout store (R12 verbatim).
// grid (8, 16, 2): 16 batches per launch.
// ---------------------------------------------------------------------------
__global__ void __launch_bounds__(128) stdp_scan_kernel(const float* __restrict__ pre,
                                                        const float* __restrict__ post,
                                                        int b0)
{
    const int side = blockIdx.z;
    const float* __restrict__ in = side ? post : pre;
    __nv_bfloat16* mat = side ? g_B : g_A;
    const int b   = blockIdx.y + b0;
    const int bx  = blockIdx.x;
    const int tid = threadIdx.x;
    const int p0  = bx * 128;

    const float dA = 0.95122942f;                      // exp(-1/20)
    const float dB = side ? 0.99126643f : 0.99014786f; // exp(-1/114) / exp(-1/101)
    const float c1 = side ? 0.00525f : 0.005f;         // A_MINUS / A_PLUS
    const float c2 = 0.0001f;

    __shared__ __align__(16) float         sx[4][16 * 128];
    __shared__ __align__(16) __nv_bfloat16 s1[128][24];
    __shared__ __align__(16) __nv_bfloat16 s2[128][24];

    const float* base = in + (size_t)b * (512 * 1024) + p0;
    const uint32_t sxb = smem_u32(sx);

    auto fill = [&](int ch, int s) {
        const float* g = base + (size_t)ch * 16 * 1024;
        uint32_t st = sxb + (uint32_t)s * (16 * 128 * 4);
        #pragma unroll
        for (int i = 0; i < 4; ++i) {
            int idx = tid + i * 128;
            int r = idx >> 5, j = idx & 31;
            cp16(st + (uint32_t)(r * 512 + j * 16), g + (size_t)r * 1024 + j * 4);
        }
    };

    #pragma unroll
    for (int f = 0; f < 3; ++f) {
        fill(f, f);
        asm volatile("cp.async.commit_group;" ::: "memory");
    }

    float t1 = 0.f, t2 = 0.f;

    for (int ch = 0; ch < 32; ++ch) {
        asm volatile("cp.async.wait_group 2;" ::: "memory");
        __syncthreads();
        if (ch + 3 < 32) fill(ch + 3, (ch + 3) & 3);
        asm volatile("cp.async.commit_group;" ::: "memory");

        const float* x_s = sx[ch & 3];
        #pragma unroll
        for (int tt = 0; tt < 16; ++tt) {
            float x = x_s[tt * 128 + tid];
            t1 *= dA; t2 *= dB;
            float tr = fmaf(c2 * t1, t2, c1 * t1);
            s1[tid][tt] = __float2bfloat16(side ? x : tr);
            s2[tid][tt] = __float2bfloat16(side ? -tr : x);
            t1 += x; t2 += x;
        }
        __syncthreads();

        const int ks = b * 32 + ch;
        uint4* mat4 = reinterpret_cast<uint4*>(mat);
        #pragma unroll
        for (int it = 0; it < 2; ++it) {
            int f    = it * 128 + tid;
            int lane = f & 31;
            int frag = f >> 5;
            int gid  = lane >> 2, tig = lane & 3;
            int pr   = frag * 16 + gid;
            int tb   = tig * 2;
            uint4 w1, w2;
            w1.x = *(const uint32_t*)&s1[pr    ][tb    ];
            w1.y = *(const uint32_t*)&s1[pr + 8][tb    ];
            w1.z = *(const uint32_t*)&s1[pr    ][tb + 8];
            w1.w = *(const uint32_t*)&s1[pr + 8][tb + 8];
            w2.x = *(const uint32_t*)&s2[pr    ][tb    ];
            w2.y = *(const uint32_t*)&s2[pr + 8][tb    ];
            w2.z = *(const uint32_t*)&s2[pr    ][tb + 8];
            w2.w = *(const uint32_t*)&s2[pr + 8][tb + 8];
            size_t d16, half;
            if (side == 0) {
                d16  = ((size_t)(bx * 2048 + ks) * 8 + frag) * 32 + lane;
                half = 1024ull * 8 * 32;
            } else {
                d16  = ((size_t)((bx >> 1) * 2048 + ks) * 16 + (bx & 1) * 8 + frag) * 32 + lane;
                half = 1024ull * 16 * 32;
            }
            mat4[d16]        = w1;
            mat4[d16 + half] = w2;
        }
    }
}

// ---------------------------------------------------------------------------
// Kernel 2: warp-specialized bf16 mma.sync GEMM. CTA 128x256, 320 threads:
// warps 0-7 consumers (2Mx4N, warp tile 64x64), warps 8-9 producers.
// 4-stage mbarrier ring over 48KB k64 chunks. Split-K=8 -> 64 chunks/CTA.
// grid (8,4,4)/pass: pass 0 -> slices {0,1,4,5}; pass 1 -> {2,3,6,7}.
// ---------------------------------------------------------------------------
constexpr int      CHUNK_U4    = 3072;                       // 1024 A + 2048 B uint4
constexpr uint32_t GEMM_SMEM_B = 4 * CHUNK_U4 * 16;          // 196608 B

__global__ void __launch_bounds__(320, 1) stdp_gemm_kernel(int pass)
{
    extern __shared__ __align__(16) uint4 sm[];              // [4][3072]
    __shared__ __align__(8) unsigned long long mbar_s[8];    // [0..3] full, [4..7] empty
    const int tid  = threadIdx.x;
    const int lane = tid & 31;
    const int wid  = tid >> 5;
    const int mt   = blockIdx.x;
    const int nt   = blockIdx.y;
    const int z    = blockIdx.z;
    const int slice = (pass << 1) + (z & 1) + ((z >> 1) << 2); // {0,1,4,5}/{2,3,6,7}

    const uint4* gA = reinterpret_cast<const uint4*>(g_A)
                    + (size_t)(mt * 2048 + slice * 256) * 8 * 32;
    const uint4* gB = reinterpret_cast<const uint4*>(g_B)
                    + (size_t)(nt * 2048 + slice * 256) * 16 * 32;

    const uint32_t smb = smem_u32(sm);
    const uint32_t mb  = smem_u32(mbar_s);

    if (tid == 0) {
        #pragma unroll
        for (int s = 0; s < 4; ++s) mbar_init(mb + 8 * s, 64);       // full: 64 prod threads
        #pragma unroll
        for (int s = 0; s < 4; ++s) mbar_init(mb + 32 + 8 * s, 8);   // empty: 8 cons warps
    }
    __syncthreads();

    if (wid >= 8) {
        // ---------------- producer warps (64 threads) ----------------
        const int ptid = tid - 256;                    // 0..63
        for (int c = 0; c < 64; ++c) {
            const int s = c & 3;
            if (c >= 4) mbar_wait(mb + 32 + 8 * s, (uint32_t)(((c >> 2) - 1) & 1));
            uint32_t stA = smb + (uint32_t)s * (CHUNK_U4 * 16);
            uint32_t stB = stA + 1024 * 16;
            const uint4* srcA = gA + (size_t)c * 1024;
            const uint4* srcB = gB + (size_t)c * 2048;
            #pragma unroll
            for (int i = 0; i < 16; ++i)
                cp16(stA + (uint32_t)(ptid + i * 64) * 16, srcA + ptid + i * 64);
            #pragma unroll
            for (int i = 0; i < 32; ++i)
                cp16(stB + (uint32_t)(ptid + i * 64) * 16, srcB + ptid + i * 64);
            // NOINC: completion counts against the init(64) expectation.
            cp_async_mbar_arrive_noinc(mb + 8 * s);
        }
        return;
    }

    // ---------------- consumer warps (8 warps, 2Mx4N) ----------------
    const int wm = wid & 1;
    const int wn = wid >> 1;

    auto aAddr = [&](int st, int ksl, int i) -> const uint4* {
        return sm + st * CHUNK_U4 + (size_t)(ksl * 8 + wm * 4 + i) * 32 + lane;
    };
    auto bAddr = [&](int st, int ksl, int j) -> const uint4* {
        return sm + st * CHUNK_U4 + 1024 + (size_t)(ksl * 16 + wn * 4 + j) * 32 + lane;
    };

    float acc[4][8][4];
    #pragma unroll
    for (int i = 0; i < 4; ++i)
        #pragma unroll
        for (int j = 0; j < 8; ++j)
            #pragma unroll
            for (int c = 0; c < 4; ++c) acc[i][j][c] = 0.f;

    for (int c = 0; c < 64; ++c) {
        const int s = c & 3;
        mbar_wait(mb + 8 * s, (uint32_t)((c >> 2) & 1));   // full[s], acquire

        #pragma unroll
        for (int ksl = 0; ksl < 4; ++ksl) {
            uint4 af[4], bf[4];
            #pragma unroll
            for (int i = 0; i < 4; ++i) af[i] = *aAddr(s, ksl, i);
            #pragma unroll
            for (int j = 0; j < 4; ++j) bf[j] = *bAddr(s, ksl, j);
            #pragma unroll
            for (int i = 0; i < 4; ++i) {
                const uint32_t* a = reinterpret_cast<const uint32_t*>(&af[i]);
                #pragma unroll
                for (int j = 0; j < 4; ++j) {
                    mma_bf16(acc[i][2 * j + 0], a, bf[j].x, bf[j].z); // even n8
                    mma_bf16(acc[i][2 * j + 1], a, bf[j].y, bf[j].w); // odd n8
                }
            }
        }
        if (lane == 0) mbar_arrive(mb + 32 + 8 * s);       // empty[s], release
    }

    const int gid = lane >> 2, tig = lane & 3;
    float* wsbase = g_WS + ((size_t)slice << 20);
    #pragma unroll
    for (int i = 0; i < 4; ++i) {
        int row0 = mt * 128 + (wm * 4 + i) * 16 + gid;
        #pragma unroll
        for (int j = 0; j < 8; ++j) {
            int col = nt * 256 + (wn * 4 + (j >> 1)) * 16 + (j & 1) * 8 + tig * 2;
            float* d0 = wsbase + (size_t)row0 * 1024 + col;
            d0[0] = acc[i][j][0];
            d0[1] = acc[i][j][1];
            float* d1 = d0 + 8 * 1024;
            d1[0] = acc[i][j][2];
            d1[1] = acc[i][j][3];
        }
    }
}

// ---------------------------------------------------------------------------
// Kernel 3: reduce 8 split-K partials + scale 1/(B*T). Deterministic.
// ---------------------------------------------------------------------------
__global__ void __launch_bounds__(256) stdp_reduce_kernel(float* __restrict__ out)
{
    int i = blockIdx.x * 256 + threadIdx.x;
    const float4* w = reinterpret_cast<const float4*>(g_WS);
    float x = 0.f, y = 0.f, z = 0.f, u = 0.f;
    #pragma unroll
    for (int j = 0; j < 8; ++j) {
        float4 v = w[i + j * 262144];
        x += v.x; y += v.y; z += v.z; u += v.w;
    }
    const float s = 1.0f / 16384.0f;
    float4 r; r.x = x * s; r.y = y * s; r.z = z * s; r.w = u * s;
    reinterpret_cast<float4*>(out)[i] = r;
}

// ---------------------------------------------------------------------------
extern "C" void kernel_launch(void* const* d_in, const int* in_sizes, int n_in,
                              void* d_out, int out_size)
{
    (void)in_sizes; (void)n_in; (void)out_size;
    const float* pre  = (const float*)d_in[0];
    const float* post = (const float*)d_in[1];
    float* out = (float*)d_out;

    static cudaStream_t s1 = nullptr;
    static cudaEvent_t ev0 = nullptr, ev1 = nullptr, ev2 = nullptr;
    if (s1 == nullptr) {
        cudaStreamCreateWithFlags(&s1, cudaStreamNonBlocking);
        cudaEventCreateWithFlags(&ev0, cudaEventDisableTiming);
        cudaEventCreateWithFlags(&ev1, cudaEventDisableTiming);
        cudaEventCreateWithFlags(&ev2, cudaEventDisableTiming);
        cudaFuncSetAttribute(stdp_gemm_kernel,
                             cudaFuncAttributeMaxDynamicSharedMemorySize, GEMM_SMEM_B);
    }

    // scan batches 0-15 (enables K slices {0,1,4,5})
    stdp_scan_kernel<<<dim3(8, 16, 2), 128>>>(pre, post, 0);
    cudaEventRecord(ev0, 0);
    cudaStreamWaitEvent(s1, ev0, 0);

    // GEMM pass 0 on stream s1, overlapping scan of batches 16-31 below
    stdp_gemm_kernel<<<dim3(8, 4, 4), 320, GEMM_SMEM_B, s1>>>(0);

    stdp_scan_kernel<<<dim3(8, 16, 2), 128>>>(pre, post, 16);
    cudaEventRecord(ev1, 0);
    cudaStreamWaitEvent(s1, ev1, 0);

    // GEMM pass 1 (slices {2,3,6,7})
    stdp_gemm_kernel<<<dim3(8, 4, 4), 320, GEMM_SMEM_B, s1>>>(1);
    cudaEventRecord(ev2, s1);
    cudaStreamWaitEvent(0, ev2, 0);

    stdp_reduce_kernel<<<1024, 256>>>(out);
}

// round 16
// speedup vs baseline: 1.2000x; 1.2000x over previous
#include <cuda_runtime.h>
#include <cuda_bf16.h>
#include <cstdint>
#include <cstddef>

// ============================================================================
// TripletSTDP: B=32, T=512, N_PRE=N_POST=1024.
// wu = (1/(B*T)) * (A @ B^T), K = 2*B*T = 32768
// K layout (ours to choose): k = phase*8192 + b*256 + t_local   (first half)
//                            k = 16384 + same                    (second half)
//   A[m][k]: first half -> R trace of pre (decayed), second -> pre spike
//   B[n][k]: first half -> post spike,               second -> -O trace
// A/B PRE-PERMUTED in mma.m16n8k16 fragment order (bf16).
// Timeline: scanP0(t0-255, all batches, full occupancy) ->
//   [gemmA slices {0,1,4,5} || scanP1(t256-511)] ->
//   [gemmB slices {2,3,6,7} || reduce0(slices of A)] -> reduce1 -> out.
// GEMM = R12 super-chunked bulk-synchronous kernel (proven ceiling).
// ============================================================================

static __device__ __align__(128) __nv_bfloat16 g_A[1024ull * 32768ull]; // 64 MB
static __device__ __align__(128) __nv_bfloat16 g_B[1024ull * 32768ull]; // 64 MB
static __device__ __align__(128) float g_WS[8ull * 1024ull * 1024ull];  // 8 split-K partials
static __device__ __align__(128) float g_R0[1024ull * 1024ull];         // reduce0 temp
static __device__ float g_c1[65536];                                    // scan carry t1
static __device__ float g_c2[65536];                                    // scan carry t2

// ---------------------------------------------------------------------------
__device__ __forceinline__ void mma_bf16(float* d, const uint32_t* a,
                                         uint32_t b0, uint32_t b1) {
    asm volatile(
        "mma.sync.aligned.m16n8k16.row.col.f32.bf16.bf16.f32 "
        "{%0,%1,%2,%3}, {%4,%5,%6,%7}, {%8,%9}, {%0,%1,%2,%3};"
        : "+f"(d[0]), "+f"(d[1]), "+f"(d[2]), "+f"(d[3])
        : "r"(a[0]), "r"(a[1]), "r"(a[2]), "r"(a[3]), "r"(b0), "r"(b1));
}
__device__ __forceinline__ uint32_t smem_u32(const void* p) {
    uint32_t a;
    asm("{ .reg .u64 t; cvta.to.shared.u64 t, %1; cvt.u32.u64 %0, t; }" : "=r"(a) : "l"(p));
    return a;
}
__device__ __forceinline__ void cp16(uint32_t dst, const void* src) {
    asm volatile("cp.async.cg.shared.global [%0], [%1], 16;" :: "r"(dst), "l"(src));
}

// ---------------------------------------------------------------------------
// Kernel 1: trace scan phase p (t in [256p, 256p+256)), ALL batches/sides.
// grid (8, 32, 2) = 512 CTAs (full occupancy both phases), 128 threads.
// 16 chunks of 16 t-steps; carry (t1,t2) through g_c1/g_c2 between phases.
// k16-step index: ks = p*512 + b*16 + ch   (t-consecutive within CTA).
// ---------------------------------------------------------------------------
__global__ void __launch_bounds__(128) stdp_scan_kernel(const float* __restrict__ pre,
                                                        const float* __restrict__ post,
                                                        int p)
{
    const int side = blockIdx.z;
    const float* __restrict__ in = side ? post : pre;
    __nv_bfloat16* mat = side ? g_B : g_A;
    const int b   = blockIdx.y;
    const int bx  = blockIdx.x;
    const int tid = threadIdx.x;
    const int p0  = bx * 128;

    const float dA = 0.95122942f;                      // exp(-1/20)
    const float dB = side ? 0.99126643f : 0.99014786f; // exp(-1/114) / exp(-1/101)
    const float c1 = side ? 0.00525f : 0.005f;         // A_MINUS / A_PLUS
    const float c2 = 0.0001f;

    __shared__ __align__(16) float         sx[4][16 * 128];
    __shared__ __align__(16) __nv_bfloat16 s1[128][24];
    __shared__ __align__(16) __nv_bfloat16 s2[128][24];

    const float* base = in + (size_t)b * (512 * 1024) + (size_t)p * (256 * 1024) + p0;
    const uint32_t sxb = smem_u32(sx);

    auto fill = [&](int ch, int s) {
        const float* g = base + (size_t)ch * 16 * 1024;
        uint32_t st = sxb + (uint32_t)s * (16 * 128 * 4);
        #pragma unroll
        for (int i = 0; i < 4; ++i) {
            int idx = tid + i * 128;
            int r = idx >> 5, j = idx & 31;
            cp16(st + (uint32_t)(r * 512 + j * 16), g + (size_t)r * 1024 + j * 4);
        }
    };

    #pragma unroll
    for (int f = 0; f < 3; ++f) {
        fill(f, f);
        asm volatile("cp.async.commit_group;" ::: "memory");
    }

    const int cid = side * 32768 + b * 1024 + p0 + tid;
    float t1 = 0.f, t2 = 0.f;
    if (p) { t1 = g_c1[cid]; t2 = g_c2[cid]; }

    for (int ch = 0; ch < 16; ++ch) {
        asm volatile("cp.async.wait_group 2;" ::: "memory");
        __syncthreads();
        if (ch + 3 < 16) fill(ch + 3, (ch + 3) & 3);
        asm volatile("cp.async.commit_group;" ::: "memory");

        const float* x_s = sx[ch & 3];
        #pragma unroll
        for (int tt = 0; tt < 16; ++tt) {
            float x = x_s[tt * 128 + tid];
            t1 *= dA; t2 *= dB;                          // decay first
            float tr = fmaf(c2 * t1, t2, c1 * t1);       // c1*r1 + c2*r1*r2
            s1[tid][tt] = __float2bfloat16(side ? x : tr);
            s2[tid][tt] = __float2bfloat16(side ? -tr : x);
            t1 += x; t2 += x;                            // then add spike
        }
        __syncthreads();

        const int ks = p * 512 + b * 16 + ch;            // global k16-step index
        uint4* mat4 = reinterpret_cast<uint4*>(mat);
        #pragma unroll
        for (int it = 0; it < 2; ++it) {
            int f    = it * 128 + tid;
            int lane = f & 31;
            int frag = f >> 5;
            int gid  = lane >> 2, tig = lane & 3;
            int pr   = frag * 16 + gid;
            int tb   = tig * 2;
            uint4 w1, w2;
            w1.x = *(const uint32_t*)&s1[pr    ][tb    ];
            w1.y = *(const uint32_t*)&s1[pr + 8][tb    ];
            w1.z = *(const uint32_t*)&s1[pr    ][tb + 8];
            w1.w = *(const uint32_t*)&s1[pr + 8][tb + 8];
            w2.x = *(const uint32_t*)&s2[pr    ][tb    ];
            w2.y = *(const uint32_t*)&s2[pr + 8][tb    ];
            w2.z = *(const uint32_t*)&s2[pr    ][tb + 8];
            w2.w = *(const uint32_t*)&s2[pr + 8][tb + 8];
            size_t d16, half;
            if (side == 0) {   // A layout
                d16  = ((size_t)(bx * 2048 + ks) * 8 + frag) * 32 + lane;
                half = 1024ull * 8 * 32;
            } else {           // B layout
                d16  = ((size_t)((bx >> 1) * 2048 + ks) * 16 + (bx & 1) * 8 + frag) * 32 + lane;
                half = 1024ull * 16 * 32;
            }
            mat4[d16]        = w1;
            mat4[d16 + half] = w2;
        }
    }
    if (!p) { g_c1[cid] = t1; g_c2[cid] = t2; }
}

// ---------------------------------------------------------------------------
// Kernel 2: bf16 mma.sync GEMM, super-chunked (R12 verbatim — proven best).
// CTA 128x256, 8 warps (2Mx4N), warp tile 64x64. Split-K=8 (64 chunks =
// 32 super-steps/pass). grid (8,4,4)/pass: pass0 {0,1,4,5}; pass1 {2,3,6,7}.
// ---------------------------------------------------------------------------
constexpr int      CHUNK_U4    = 3072;                       // 1024 A + 2048 B uint4
constexpr uint32_t GEMM_SMEM_B = 4 * CHUNK_U4 * 16;          // 196608 B

__global__ void __launch_bounds__(256, 1) stdp_gemm_kernel(int pass)
{
    extern __shared__ __align__(16) uint4 sm[];              // [4][3072]
    const int tid  = threadIdx.x;
    const int lane = tid & 31;
    const int wid  = tid >> 5;
    const int wm   = wid & 1;
    const int wn   = wid >> 1;
    const int mt   = blockIdx.x;
    const int nt   = blockIdx.y;
    const int z    = blockIdx.z;
    const int slice = (pass << 1) + (z & 1) + ((z >> 1) << 2); // {0,1,4,5}/{2,3,6,7}

    const uint4* gA = reinterpret_cast<const uint4*>(g_A)
                    + (size_t)(mt * 2048 + slice * 256) * 8 * 32;
    const uint4* gB = reinterpret_cast<const uint4*>(g_B)
                    + (size_t)(nt * 2048 + slice * 256) * 16 * 32;

    const uint32_t smb = smem_u32(sm);

    auto fill = [&](int c, int st) {
        uint32_t stA = smb + (uint32_t)st * (CHUNK_U4 * 16);
        uint32_t stB = stA + 1024 * 16;
        const uint4* srcA = gA + (size_t)c * 1024;
        const uint4* srcB = gB + (size_t)c * 2048;
        #pragma unroll
        for (int i = 0; i < 4; ++i)
            cp16(stA + (uint32_t)(tid + i * 256) * 16, srcA + tid + i * 256);
        #pragma unroll
        for (int i = 0; i < 8; ++i)
            cp16(stB + (uint32_t)(tid + i * 256) * 16, srcB + tid + i * 256);
    };
    auto aAddr = [&](int st, int ksl, int i) -> const uint4* {
        return sm + st * CHUNK_U4 + (size_t)(ksl * 8 + wm * 4 + i) * 32 + lane;
    };
    auto bAddr = [&](int st, int ksl, int j) -> const uint4* {
        return sm + st * CHUNK_U4 + 1024 + (size_t)(ksl * 16 + wn * 4 + j) * 32 + lane;
    };

    float acc[4][8][4];
    #pragma unroll
    for (int i = 0; i < 4; ++i)
        #pragma unroll
        for (int j = 0; j < 8; ++j)
            #pragma unroll
            for (int c = 0; c < 4; ++c) acc[i][j][c] = 0.f;

    fill(0, 0);
    fill(1, 1);
    asm volatile("cp.async.commit_group;" ::: "memory");
    asm volatile("cp.async.wait_group 0;" ::: "memory");
    __syncthreads();

    uint4 af[2][4], bf[2][4];
    #pragma unroll
    for (int i = 0; i < 4; ++i) af[0][i] = *aAddr(0, 0, i);
    #pragma unroll
    for (int j = 0; j < 4; ++j) bf[0][j] = *bAddr(0, 0, j);

    for (int s = 0; s < 32; ++s) {
        const int p = s & 1;
        if (s < 31) {
            fill(2 * s + 2, 2 * (p ^ 1));
            fill(2 * s + 3, 2 * (p ^ 1) + 1);
        }
        asm volatile("cp.async.commit_group;" ::: "memory");

        #pragma unroll
        for (int u = 0; u < 8; ++u) {
            const int cur = u & 1;
            const int nxt = cur ^ 1;
            const int pu  = (u < 7) ? (u + 1) : 7;     // u=7: dead prefetch (safe)
            const int pst = 2 * p + (pu >> 2);
            const int pk  = pu & 3;
            #pragma unroll
            for (int i = 0; i < 4; ++i) af[nxt][i] = *aAddr(pst, pk, i);
            #pragma unroll
            for (int j = 0; j < 4; ++j) bf[nxt][j] = *bAddr(pst, pk, j);
            #pragma unroll
            for (int i = 0; i < 4; ++i) {
                const uint32_t* a = reinterpret_cast<const uint32_t*>(&af[cur][i]);
                #pragma unroll
                for (int j = 0; j < 4; ++j) {
                    mma_bf16(acc[i][2 * j + 0], a, bf[cur][j].x, bf[cur][j].z);
                    mma_bf16(acc[i][2 * j + 1], a, bf[cur][j].y, bf[cur][j].w);
                }
            }
        }

        asm volatile("cp.async.wait_group 0;" ::: "memory");
        __syncthreads();
        if (s < 31) {
            const int nst = 2 * (p ^ 1);
            #pragma unroll
            for (int i = 0; i < 4; ++i) af[0][i] = *aAddr(nst, 0, i);
            #pragma unroll
            for (int j = 0; j < 4; ++j) bf[0][j] = *bAddr(nst, 0, j);
        }
    }

    const int gid = lane >> 2, tig = lane & 3;
    float* wsbase = g_WS + ((size_t)slice << 20);
    #pragma unroll
    for (int i = 0; i < 4; ++i) {
        int row0 = mt * 128 + (wm * 4 + i) * 16 + gid;
        #pragma unroll
        for (int j = 0; j < 8; ++j) {
            int col = nt * 256 + (wn * 4 + (j >> 1)) * 16 + (j & 1) * 8 + tig * 2;
            float* d0 = wsbase + (size_t)row0 * 1024 + col;
            d0[0] = acc[i][j][0];
            d0[1] = acc[i][j][1];
            float* d1 = d0 + 8 * 1024;
            d1[0] = acc[i][j][2];
            d1[1] = acc[i][j][3];
        }
    }
}

// ---------------------------------------------------------------------------
// Kernel 3a: reduce0 — sum slices {0,1,4,5} into g_R0 (runs under gemmB).
// Kernel 3b: reduce1 — add slices {2,3,6,7}, scale, write out.
// ---------------------------------------------------------------------------
__global__ void __launch_bounds__(256) stdp_reduce0_kernel()
{
    int i = blockIdx.x * 256 + threadIdx.x;      // float4 units
    const float4* w = reinterpret_cast<const float4*>(g_WS);
    float4 a = w[i];
    float4 b = w[i + 1 * 262144];
    float4 c = w[i + 4 * 262144];
    float4 d = w[i + 5 * 262144];
    float4 r;
    r.x = (a.x + b.x) + (c.x + d.x);
    r.y = (a.y + b.y) + (c.y + d.y);
    r.z = (a.z + b.z) + (c.z + d.z);
    r.w = (a.w + b.w) + (c.w + d.w);
    reinterpret_cast<float4*>(g_R0)[i] = r;
}

__global__ void __launch_bounds__(256) stdp_reduce1_kernel(float* __restrict__ out)
{
    int i = blockIdx.x * 256 + threadIdx.x;
    const float4* w = reinterpret_cast<const float4*>(g_WS);
    float4 a = w[i + 2 * 262144];
    float4 b = w[i + 3 * 262144];
    float4 c = w[i + 6 * 262144];
    float4 d = w[i + 7 * 262144];
    float4 r0 = reinterpret_cast<const float4*>(g_R0)[i];
    const float s = 1.0f / 16384.0f;
    float4 r;
    r.x = (r0.x + (a.x + b.x) + (c.x + d.x)) * s;
    r.y = (r0.y + (a.y + b.y) + (c.y + d.y)) * s;
    r.z = (r0.z + (a.z + b.z) + (c.z + d.z)) * s;
    r.w = (r0.w + (a.w + b.w) + (c.w + d.w)) * s;
    reinterpret_cast<float4*>(out)[i] = r;
}

// ---------------------------------------------------------------------------
extern "C" void kernel_launch(void* const* d_in, const int* in_sizes, int n_in,
                              void* d_out, int out_size)
{
    (void)in_sizes; (void)n_in; (void)out_size;
    const float* pre  = (const float*)d_in[0];
    const float* post = (const float*)d_in[1];
    float* out = (float*)d_out;

    static cudaStream_t s1 = nullptr;
    static cudaEvent_t ev0 = nullptr, ev1 = nullptr, evA = nullptr, evB = nullptr;
    if (s1 == nullptr) {
        cudaStreamCreateWithFlags(&s1, cudaStreamNonBlocking);
        cudaEventCreateWithFlags(&ev0, cudaEventDisableTiming);
        cudaEventCreateWithFlags(&ev1, cudaEventDisableTiming);
        cudaEventCreateWithFlags(&evA, cudaEventDisableTiming);
        cudaEventCreateWithFlags(&evB, cudaEventDisableTiming);
        cudaFuncSetAttribute(stdp_gemm_kernel,
                             cudaFuncAttributeMaxDynamicSharedMemorySize, GEMM_SMEM_B);
    }

    // scan phase 0 (t 0-255, all batches): enables slices {0,1,4,5}
    stdp_scan_kernel<<<dim3(8, 32, 2), 128>>>(pre, post, 0);
    cudaEventRecord(ev0, 0);
    cudaStreamWaitEvent(s1, ev0, 0);

    // GEMM pass 0 on s1, overlapping scan phase 1 on stream 0
    stdp_gemm_kernel<<<dim3(8, 4, 4), 256, GEMM_SMEM_B, s1>>>(0);
    cudaEventRecord(evA, s1);

    stdp_scan_kernel<<<dim3(8, 32, 2), 128>>>(pre, post, 1);
    cudaEventRecord(ev1, 0);
    cudaStreamWaitEvent(s1, ev1, 0);

    // GEMM pass 1 on s1; reduce0 (pass-0 slices) overlaps on stream 0
    stdp_gemm_kernel<<<dim3(8, 4, 4), 256, GEMM_SMEM_B, s1>>>(1);
    cudaStreamWaitEvent(0, evA, 0);
    stdp_reduce0_kernel<<<1024, 256>>>();
    cudaEventRecord(evB, s1);
    cudaStreamWaitEvent(0, evB, 0);

    stdp_reduce1_kernel<<<1024, 256>>>(out);
}